// round 16
// baseline (speedup 1.0000x reference)
#include <cuda_runtime.h>
#include <cuda_fp16.h>
#include <cstdint>

// MoELayer: B=2, T=2048, C=1024, E=8, H=4096, TOP_K=2
#define NT   4096
#define CDIM 1024
#define HDIM 4096
#define NEXP 8

#define BM 128
#define BN 128
#define KC 64                   // k-elements per chunk
#define ROWE 72                 // A tile row stride (fp16 elems): 64 + 8 pad
#define ROWB 136                // B tile row stride (fp16 elems): 128 + 8 pad
#define TILEA_E (128 * ROWE)    // A tile elems (128 m-rows x KC)
#define TILEB_E (64 * ROWB)     // B tile elems (KC k-rows x BN)
#define STAGE_E (TILEA_E + TILEB_E)
#define NSTAGE 3
#define SMEM_DYN (NSTAGE * STAGE_E * 2)   // 3 stages = 107520 B

// ---------------- scratch (device globals) --------------------------------
__device__ int   g_counts[NEXP];
__device__ int   g_buckets[NEXP * NT];            // entry = token*2 + slot
__device__ float g_gatew[NT * 2];
__device__ __half g_x_h[NT * CDIM];
__device__ __half g_wfc16[(size_t)NEXP * CDIM * HDIM];  // [E][C][H] (as input)
__device__ __half g_wpr16[(size_t)NEXP * HDIM * CDIM];  // [E][H][C] (as input)
__device__ __half g_h[(size_t)2 * NT * HDIM];           // [entry][H]

// ---------------- host-side streams/events (created pre-main) --------------
struct SideStreams {
    cudaStream_t s1, s2, s3;
    cudaEvent_t evFork, evW0a, evW0b, evW1a, evW1b, evCX, evG1a, evG2a;
    SideStreams() {
        cudaStreamCreateWithFlags(&s1, cudaStreamNonBlocking);
        cudaStreamCreateWithFlags(&s2, cudaStreamNonBlocking);
        cudaStreamCreateWithFlags(&s3, cudaStreamNonBlocking);
        cudaEventCreateWithFlags(&evFork, cudaEventDisableTiming);
        cudaEventCreateWithFlags(&evW0a, cudaEventDisableTiming);
        cudaEventCreateWithFlags(&evW0b, cudaEventDisableTiming);
        cudaEventCreateWithFlags(&evW1a, cudaEventDisableTiming);
        cudaEventCreateWithFlags(&evW1b, cudaEventDisableTiming);
        cudaEventCreateWithFlags(&evCX, cudaEventDisableTiming);
        cudaEventCreateWithFlags(&evG1a, cudaEventDisableTiming);
        cudaEventCreateWithFlags(&evG2a, cudaEventDisableTiming);
    }
};
static SideStreams g_ss;

// ---------------- asm helpers ---------------------------------------------
__device__ __forceinline__ uint32_t smem_u32(const void* p) {
    uint32_t a;
    asm("{ .reg .u64 t; cvta.to.shared.u64 t, %1; cvt.u32.u64 %0, t; }"
        : "=r"(a) : "l"(p));
    return a;
}
__device__ __forceinline__ void cp16(uint32_t dst, const void* src, int sz) {
    asm volatile("cp.async.cg.shared.global [%0], [%1], 16, %2;"
                 :: "r"(dst), "l"(src), "r"(sz));
}
#define CP_COMMIT() asm volatile("cp.async.commit_group;" ::: "memory")
#define CP_WAIT(n)  asm volatile("cp.async.wait_group %0;" :: "n"(n) : "memory")
__device__ __forceinline__ void ldm_x4(uint32_t* r, uint32_t a) {
    asm volatile("ldmatrix.sync.aligned.m8n8.x4.shared.b16 {%0,%1,%2,%3}, [%4];"
                 : "=r"(r[0]), "=r"(r[1]), "=r"(r[2]), "=r"(r[3]) : "r"(a));
}
__device__ __forceinline__ void ldm_x4_trans(uint32_t* r, uint32_t a) {
    asm volatile(
        "ldmatrix.sync.aligned.m8n8.x4.trans.shared.b16 {%0,%1,%2,%3}, [%4];"
        : "=r"(r[0]), "=r"(r[1]), "=r"(r[2]), "=r"(r[3]) : "r"(a));
}
__device__ __forceinline__ void mma_fp16(float* c, const uint32_t* a,
                                         const uint32_t* b) {
    asm volatile(
        "mma.sync.aligned.m16n8k16.row.col.f32.f16.f16.f32 "
        "{%0,%1,%2,%3},{%4,%5,%6,%7},{%8,%9},{%0,%1,%2,%3};"
        : "+f"(c[0]), "+f"(c[1]), "+f"(c[2]), "+f"(c[3])
        : "r"(a[0]), "r"(a[1]), "r"(a[2]), "r"(a[3]), "r"(b[0]), "r"(b[1]));
}

// ---------------- init / router -------------------------------------------
__global__ void init_kernel() { if (threadIdx.x < NEXP) g_counts[threadIdx.x] = 0; }

__global__ __launch_bounds__(64) void router_kernel(const float* __restrict__ x,
                                                    const float* __restrict__ rw) {
    int warp = (blockIdx.x * blockDim.x + threadIdx.x) >> 5;
    int lane = threadIdx.x & 31;
    if (warp >= NT) return;
    const float* xt = x + (size_t)warp * CDIM;
    float xr[32];
    #pragma unroll
    for (int kk = 0; kk < 32; kk++) xr[kk] = xt[lane + kk * 32];
    float logits[NEXP];
    #pragma unroll
    for (int e = 0; e < NEXP; e++) {
        const float* w = rw + e * CDIM;
        float s = 0.f;
        #pragma unroll
        for (int kk = 0; kk < 32; kk++) s += xr[kk] * w[lane + kk * 32];
        #pragma unroll
        for (int o = 16; o > 0; o >>= 1) s += __shfl_xor_sync(0xffffffffu, s, o);
        logits[e] = s;
    }
    float mx = logits[0];
    #pragma unroll
    for (int e = 1; e < NEXP; e++) mx = fmaxf(mx, logits[e]);
    float p[NEXP], sum = 0.f;
    #pragma unroll
    for (int e = 0; e < NEXP; e++) { p[e] = expf(logits[e] - mx); sum += p[e]; }
    #pragma unroll
    for (int e = 0; e < NEXP; e++) p[e] /= sum;
    int i0 = 0;
    #pragma unroll
    for (int e = 1; e < NEXP; e++) if (p[e] > p[i0]) i0 = e;
    int i1 = -1;
    #pragma unroll
    for (int e = 0; e < NEXP; e++) {
        if (e == i0) continue;
        if (i1 < 0 || p[e] > p[i1]) i1 = e;
    }
    float w0 = p[i0], w1 = p[i1], t = w0 + w1;
    if (lane == 0) {
        g_gatew[warp * 2 + 0] = w0 / t;
        g_gatew[warp * 2 + 1] = w1 / t;
        int p0 = atomicAdd(&g_counts[i0], 1);
        g_buckets[i0 * NT + p0] = warp * 2 + 0;
        int p1 = atomicAdd(&g_counts[i1], 1);
        g_buckets[i1 * NT + p1] = warp * 2 + 1;
    }
}

// ---------------- prep: streaming fp32 -> fp16 conversions -----------------
__global__ void convert_x_kernel(const float* __restrict__ x) {
    int i = blockIdx.x * blockDim.x + threadIdx.x;
    if (i >= NT * CDIM) return;
    g_x_h[i] = __float2half(x[i]);
}

// Destination pointers resolved IN DEVICE CODE (host-side &__device__ symbol
// is the host shadow address; GB300 ATS makes that a silent host write).
template <int W>
__global__ void convert_w_kernel(const float* __restrict__ src, size_t off) {
    __half* dst = W ? g_wpr16 : g_wfc16;
    size_t i = off + ((size_t)blockIdx.x * blockDim.x + threadIdx.x) * 8;
    float4 a = *(const float4*)(src + i);
    float4 b = *(const float4*)(src + i + 4);
    __half hb[8];
    hb[0] = __float2half(a.x); hb[1] = __float2half(a.y);
    hb[2] = __float2half(a.z); hb[3] = __float2half(a.w);
    hb[4] = __float2half(b.x); hb[5] = __float2half(b.y);
    hb[6] = __float2half(b.z); hb[7] = __float2half(b.w);
    *(uint4*)(dst + i) = *(uint4*)hb;
}

__device__ __forceinline__ float gelu_new(float v) {
    float u = v + 0.044715f * v * v * v;
    return 0.5f * v * (1.f + tanhf(0.7978845608028654f * u));
}

// ---------------- async chunk loader --------------------------------------
__device__ __forceinline__ void load_chunk_async(
    uint32_t stage_u32, const __half* __restrict__ A, int strideA, int eshift,
    const int* __restrict__ entryArr, const __half* __restrict__ B,
    int strideB, int n0, int k0, int tid) {
    #pragma unroll
    for (int t = 0; t < 4; t++) {        // A: 128 rows x 8 chunks
        int idx = tid + t * 256;
        int r = (idx >> 3) & 127;
        int c8 = idx & 7;
        uint32_t dst = stage_u32 + (r * ROWE + c8 * 8) * 2;
        int en = entryArr[r];
        if (en >= 0)
            cp16(dst, A + (size_t)(en >> eshift) * strideA + k0 + c8 * 8, 16);
        else
            cp16(dst, A, 0);             // zero-fill
    }
    #pragma unroll
    for (int t = 0; t < 4; t++) {        // B: 64 k-rows x 16 chunks (256B rows)
        int idx = tid + t * 256;
        int r = (idx >> 4) & 63;
        int c16 = idx & 15;
        uint32_t dst = stage_u32 + (TILEA_E + r * ROWB + c16 * 8) * 2;
        cp16(dst, B + (size_t)(k0 + r) * strideB + n0 + c16 * 8, 16);
    }
}

// ---------------- fused GEMM (software-pipelined fragments, split-K) ------
// P2 = 0: h = gelu(Xg @ w_fc + b_fc)  -> g_h (fp16); KS must be 1
// P2 = 1: out[token] += gate * (h @ w_proj [+ b_proj if slice 0])  (atomic)
// grid.z = (experts in launch) << LOG2KS; z encodes (expert, k-slice)
template <int P2, int LOG2KS>
__global__ __launch_bounds__(256, 2) void gemm_mma(const float* __restrict__ bias,
                                                   float* __restrict__ out,
                                                   int ebase) {
    const int NDIM = P2 ? CDIM : HDIM;
    const int KD   = P2 ? HDIM : CDIM;
    const int KS   = 1 << LOG2KS;
    const int NCHS = KD / KC / KS;       // chunks per k-slice

    int z = blockIdx.z;
    int slice = z & (KS - 1);
    int e = ebase + (z >> LOG2KS);
    int kbase = slice * NCHS;            // first chunk index of this slice

    int cnt = g_counts[e];
    int m0 = blockIdx.y * BM;
    if (m0 >= cnt) return;
    int n0 = blockIdx.x * BN;

    const __half* A = P2 ? g_h : g_x_h;
    const int eshift = P2 ? 0 : 1;
    const __half* B = P2 ? (g_wpr16 + (size_t)e * HDIM * CDIM)
                         : (g_wfc16 + (size_t)e * CDIM * HDIM);

    extern __shared__ __half sm[];
    __shared__ int entryArr[BM];
    uint32_t sbase = smem_u32(sm);

    int tid = threadIdx.x;
    int wid = tid >> 5, lane = tid & 31;
    int wm = (wid >> 2) * 64, wn = (wid & 3) * 32;
    int gr = lane >> 2, gc2 = (lane & 3) * 2;

    int a_row = (lane & 15);
    int a_cof = (lane >> 4) * 8;
    int bg = lane >> 3;
    int b_krow = (bg & 1) * 8 + (lane & 7);
    int b_ncol = (bg >> 1) * 8;

    if (tid < BM) {
        int m = m0 + tid;
        entryArr[tid] = (m < cnt) ? g_buckets[e * NT + m] : -1;
    }
    __syncthreads();

    load_chunk_async(sbase, A, KD, eshift, entryArr, B, NDIM, n0,
                     kbase * KC, tid);
    CP_COMMIT();
    load_chunk_async(sbase + (uint32_t)(STAGE_E * 2), A, KD, eshift, entryArr,
                     B, NDIM, n0, (kbase + 1) * KC, tid);
    CP_COMMIT();

    float acc[4][4][4] = {};
    int s_cur = 0, s_pf = 2;

    for (int c = 0; c < NCHS; c++) {
        CP_WAIT(1);
        __syncthreads();

        if (c + 2 < NCHS)
            load_chunk_async(sbase + (uint32_t)(s_pf * STAGE_E * 2), A, KD,
                             eshift, entryArr, B, NDIM, n0,
                             (kbase + c + 2) * KC, tid);
        CP_COMMIT();

        uint32_t st = sbase + (uint32_t)(s_cur * STAGE_E * 2);
        uint32_t stA = st;
        uint32_t stB = st + TILEA_E * 2;

        uint32_t bfb[2][8];
        uint32_t afb[2][4];

        {
            uint32_t r4[4];
            uint32_t boff0 = (uint32_t)(((b_krow) * ROWB + wn + b_ncol) * 2);
            ldm_x4_trans(r4, stB + boff0);
            bfb[0][0] = r4[0]; bfb[0][1] = r4[1];
            bfb[0][2] = r4[2]; bfb[0][3] = r4[3];
            uint32_t boff1 = (uint32_t)(((b_krow) * ROWB + wn + 16 + b_ncol) * 2);
            ldm_x4_trans(r4, stB + boff1);
            bfb[0][4] = r4[0]; bfb[0][5] = r4[1];
            bfb[0][6] = r4[2]; bfb[0][7] = r4[3];
        }
        ldm_x4(afb[0], stA + (uint32_t)(((wm + a_row) * ROWE + a_cof) * 2));

        #pragma unroll
        for (int s = 0; s < 4; s++) {
            int bcur = s & 1;
            if (s < 3) {
                int kofn = (s + 1) * 16;
                uint32_t r4[4];
                uint32_t boff0 = (uint32_t)(
                    ((kofn + b_krow) * ROWB + wn + b_ncol) * 2);
                ldm_x4_trans(r4, stB + boff0);
                bfb[bcur ^ 1][0] = r4[0]; bfb[bcur ^ 1][1] = r4[1];
                bfb[bcur ^ 1][2] = r4[2]; bfb[bcur ^ 1][3] = r4[3];
                uint32_t boff1 = (uint32_t)(
                    ((kofn + b_krow) * ROWB + wn + 16 + b_ncol) * 2);
                ldm_x4_trans(r4, stB + boff1);
                bfb[bcur ^ 1][4] = r4[0]; bfb[bcur ^ 1][5] = r4[1];
                bfb[bcur ^ 1][6] = r4[2]; bfb[bcur ^ 1][7] = r4[3];
            }
            int kof = s * 16;
            #pragma unroll
            for (int i = 0; i < 4; i++) {
                int acur = i & 1;
                if (i < 3) {
                    uint32_t aoff = (uint32_t)(
                        ((wm + (i + 1) * 16 + a_row) * ROWE + kof + a_cof) * 2);
                    ldm_x4(afb[acur ^ 1], stA + aoff);
                } else if (s < 3) {
                    uint32_t aoff = (uint32_t)(
                        ((wm + a_row) * ROWE + (s + 1) * 16 + a_cof) * 2);
                    ldm_x4(afb[acur ^ 1], stA + aoff);
                }
                #pragma unroll
                for (int j = 0; j < 4; j++)
                    mma_fp16(acc[i][j], afb[acur], &bfb[bcur][j * 2]);
            }
        }
        s_cur = (s_cur == 2) ? 0 : s_cur + 1;
        s_pf  = (s_pf == 2) ? 0 : s_pf + 1;
    }

    // epilogue: acc frag (row = wm+i*16+gr+h2*8, col = wn+j*8+gc2+{0,1})
    float bs[4][2];
    #pragma unroll
    for (int j = 0; j < 4; j++) {
        int n = n0 + wn + j * 8 + gc2;
        float b0 = bias[e * NDIM + n];
        float b1 = bias[e * NDIM + n + 1];
        bs[j][0] = (slice == 0) ? b0 : 0.f;   // bias only once across slices
        bs[j][1] = (slice == 0) ? b1 : 0.f;
    }
    #pragma unroll
    for (int i = 0; i < 4; i++) {
        #pragma unroll
        for (int h2 = 0; h2 < 2; h2++) {
            int lr = wm + i * 16 + gr + h2 * 8;
            int entry = entryArr[lr];
            if (entry < 0) continue;
            if (P2 == 0) {
                uint32_t* dh = (uint32_t*)(g_h + (size_t)entry * HDIM + n0 + wn);
                #pragma unroll
                for (int j = 0; j < 4; j++) {
                    float v0 = acc[i][j][h2 * 2 + 0] + bs[j][0];
                    float v1 = acc[i][j][h2 * 2 + 1] + bs[j][1];
                    __half q0 = __float2half(gelu_new(v0));
                    __half q1 = __float2half(gelu_new(v1));
                    dh[(j * 8 + gc2) >> 1] =
                        ((uint32_t)__half_as_ushort(q1) << 16) |
                        __half_as_ushort(q0);
                }
            } else {
                float ga = g_gatew[entry];
                float* yt = out + (size_t)(entry >> 1) * CDIM + n0 + wn;
                #pragma unroll
                for (int j = 0; j < 4; j++) {
                    float y0 = ga * (acc[i][j][h2 * 2 + 0] + bs[j][0]);
                    float y1 = ga * (acc[i][j][h2 * 2 + 1] + bs[j][1]);
                    atomicAdd(&yt[j * 8 + gc2], y0);
                    atomicAdd(&yt[j * 8 + gc2 + 1], y1);
                }
            }
        }
    }
}

// ---------------- launch (fork/join DAG, capture-safe) ---------------------
extern "C" void kernel_launch(void* const* d_in, const int* in_sizes, int n_in,
                              void* d_out, int out_size) {
    const float* x      = (const float*)d_in[0];
    const float* rw     = (const float*)d_in[1];
    const float* w_fc   = (const float*)d_in[2];
    const float* b_fc   = (const float*)d_in[3];
    const float* w_proj = (const float*)d_in[4];
    const float* b_proj = (const float*)d_in[5];
    float* out = (float*)d_out;

    cudaFuncSetAttribute((const void*)gemm_mma<0, 0>,
                         cudaFuncAttributeMaxDynamicSharedMemorySize, SMEM_DYN);
    cudaFuncSetAttribute((const void*)gemm_mma<1, 2>,
                         cudaFuncAttributeMaxDynamicSharedMemorySize, SMEM_DYN);

    const size_t WHALF = (size_t)(NEXP / 2) * CDIM * HDIM;
    const int WGRID = (int)(WHALF / 8 / 256);
    const dim3 G1(HDIM / BN, NT / BM, NEXP / 2);
    const dim3 G2(CDIM / BN, NT / BM, (NEXP / 2) << 2);   // split-K = 4

    // fork
    cudaEventRecord(g_ss.evFork, 0);
    cudaStreamWaitEvent(g_ss.s1, g_ss.evFork, 0);
    cudaStreamWaitEvent(g_ss.s2, g_ss.evFork, 0);
    cudaStreamWaitEvent(g_ss.s3, g_ss.evFork, 0);

    convert_w_kernel<0><<<WGRID, 256, 0, g_ss.s1>>>(w_fc, 0);
    cudaEventRecord(g_ss.evW0a, g_ss.s1);
    convert_w_kernel<0><<<WGRID, 256, 0, g_ss.s1>>>(w_fc, WHALF);
    cudaEventRecord(g_ss.evW0b, g_ss.s1);
    convert_w_kernel<1><<<WGRID, 256, 0, g_ss.s2>>>(w_proj, 0);
    cudaEventRecord(g_ss.evW1a, g_ss.s2);
    convert_w_kernel<1><<<WGRID, 256, 0, g_ss.s2>>>(w_proj, WHALF);
    cudaEventRecord(g_ss.evW1b, g_ss.s2);
    convert_x_kernel<<<(NT * CDIM + 255) / 256, 256, 0, g_ss.s3>>>(x);
    cudaMemsetAsync(out, 0, (size_t)NT * CDIM * sizeof(float), g_ss.s3);
    cudaEventRecord(g_ss.evCX, g_ss.s3);

    // main: routing
    init_kernel<<<1, 32>>>();
    router_kernel<<<NT / 2, 64>>>(x, rw);

    cudaStreamWaitEvent(0, g_ss.evW0a, 0);
    cudaStreamWaitEvent(0, g_ss.evCX, 0);
    gemm_mma<0, 0><<<G1, 256, SMEM_DYN>>>(b_fc, out, 0);
    cudaEventRecord(g_ss.evG1a, 0);

    cudaStreamWaitEvent(g_ss.s1, g_ss.evG1a, 0);
    cudaStreamWaitEvent(g_ss.s1, g_ss.evW1a, 0);
    gemm_mma<1, 2><<<G2, 256, SMEM_DYN, g_ss.s1>>>(b_proj, out, 0);
    cudaEventRecord(g_ss.evG2a, g_ss.s1);

    cudaStreamWaitEvent(0, g_ss.evW0b, 0);
    gemm_mma<0, 0><<<G1, 256, SMEM_DYN>>>(b_fc, out, 4);
    cudaStreamWaitEvent(0, g_ss.evW1b, 0);
    gemm_mma<1, 2><<<G2, 256, SMEM_DYN>>>(b_proj, out, 4);

    cudaStreamWaitEvent(0, g_ss.evG2a, 0);
}

// round 17
// speedup vs baseline: 1.0335x; 1.0335x over previous
#include <cuda_runtime.h>
#include <cuda_fp16.h>
#include <cstdint>

// MoELayer: B=2, T=2048, C=1024, E=8, H=4096, TOP_K=2
#define NT   4096
#define CDIM 1024
#define HDIM 4096
#define NEXP 8

#define BM 128
#define BN 128
#define KC 64                   // k-elements per chunk
#define ROWE 72                 // A tile row stride (fp16 elems): 64 + 8 pad
#define ROWB 136                // B tile row stride (fp16 elems): 128 + 8 pad
#define TILEA_E (128 * ROWE)    // A tile elems (128 m-rows x KC)
#define TILEB_E (64 * ROWB)     // B tile elems (KC k-rows x BN)
#define STAGE_E (TILEA_E + TILEB_E)
#define NSTAGE 3
#define SMEM_DYN (NSTAGE * STAGE_E * 2)   // 3 stages = 107520 B

// ---------------- scratch (device globals) --------------------------------
__device__ int   g_counts[NEXP];
__device__ int   g_buckets[NEXP * NT];            // entry = token*2 + slot
__device__ float g_gatew[NT * 2];
__device__ __half g_x_h[NT * CDIM];
__device__ __half g_wfc16[(size_t)NEXP * CDIM * HDIM];  // [E][C][H] (as input)
__device__ __half g_wpr16[(size_t)NEXP * HDIM * CDIM];  // [E][H][C] (as input)
__device__ __half g_h[(size_t)2 * NT * HDIM];           // [entry][H]

// ---------------- host-side streams/events (created pre-main) --------------
struct SideStreams {
    cudaStream_t s1, s2, s3;
    cudaEvent_t evFork, evW0a, evW0b, evW1a, evW1b, evCX, evG1a, evG2a;
    SideStreams() {
        cudaStreamCreateWithFlags(&s1, cudaStreamNonBlocking);
        cudaStreamCreateWithFlags(&s2, cudaStreamNonBlocking);
        cudaStreamCreateWithFlags(&s3, cudaStreamNonBlocking);
        cudaEventCreateWithFlags(&evFork, cudaEventDisableTiming);
        cudaEventCreateWithFlags(&evW0a, cudaEventDisableTiming);
        cudaEventCreateWithFlags(&evW0b, cudaEventDisableTiming);
        cudaEventCreateWithFlags(&evW1a, cudaEventDisableTiming);
        cudaEventCreateWithFlags(&evW1b, cudaEventDisableTiming);
        cudaEventCreateWithFlags(&evCX, cudaEventDisableTiming);
        cudaEventCreateWithFlags(&evG1a, cudaEventDisableTiming);
        cudaEventCreateWithFlags(&evG2a, cudaEventDisableTiming);
    }
};
static SideStreams g_ss;

// ---------------- asm helpers ---------------------------------------------
__device__ __forceinline__ uint32_t smem_u32(const void* p) {
    uint32_t a;
    asm("{ .reg .u64 t; cvta.to.shared.u64 t, %1; cvt.u32.u64 %0, t; }"
        : "=r"(a) : "l"(p));
    return a;
}
__device__ __forceinline__ void cp16(uint32_t dst, const void* src, int sz) {
    asm volatile("cp.async.cg.shared.global [%0], [%1], 16, %2;"
                 :: "r"(dst), "l"(src), "r"(sz));
}
#define CP_COMMIT() asm volatile("cp.async.commit_group;" ::: "memory")
#define CP_WAIT(n)  asm volatile("cp.async.wait_group %0;" :: "n"(n) : "memory")
__device__ __forceinline__ void ldm_x4(uint32_t* r, uint32_t a) {
    asm volatile("ldmatrix.sync.aligned.m8n8.x4.shared.b16 {%0,%1,%2,%3}, [%4];"
                 : "=r"(r[0]), "=r"(r[1]), "=r"(r[2]), "=r"(r[3]) : "r"(a));
}
__device__ __forceinline__ void ldm_x4_trans(uint32_t* r, uint32_t a) {
    asm volatile(
        "ldmatrix.sync.aligned.m8n8.x4.trans.shared.b16 {%0,%1,%2,%3}, [%4];"
        : "=r"(r[0]), "=r"(r[1]), "=r"(r[2]), "=r"(r[3]) : "r"(a));
}
__device__ __forceinline__ void mma_fp16(float* c, const uint32_t* a,
                                         const uint32_t* b) {
    asm volatile(
        "mma.sync.aligned.m16n8k16.row.col.f32.f16.f16.f32 "
        "{%0,%1,%2,%3},{%4,%5,%6,%7},{%8,%9},{%0,%1,%2,%3};"
        : "+f"(c[0]), "+f"(c[1]), "+f"(c[2]), "+f"(c[3])
        : "r"(a[0]), "r"(a[1]), "r"(a[2]), "r"(a[3]), "r"(b[0]), "r"(b[1]));
}

// ---------------- init / router -------------------------------------------
__global__ void init_kernel() { if (threadIdx.x < NEXP) g_counts[threadIdx.x] = 0; }

__global__ __launch_bounds__(64) void router_kernel(const float* __restrict__ x,
                                                    const float* __restrict__ rw) {
    int warp = (blockIdx.x * blockDim.x + threadIdx.x) >> 5;
    int lane = threadIdx.x & 31;
    if (warp >= NT) return;
    const float* xt = x + (size_t)warp * CDIM;
    float xr[32];
    #pragma unroll
    for (int kk = 0; kk < 32; kk++) xr[kk] = xt[lane + kk * 32];
    float logits[NEXP];
    #pragma unroll
    for (int e = 0; e < NEXP; e++) {
        const float* w = rw + e * CDIM;
        float s = 0.f;
        #pragma unroll
        for (int kk = 0; kk < 32; kk++) s += xr[kk] * w[lane + kk * 32];
        #pragma unroll
        for (int o = 16; o > 0; o >>= 1) s += __shfl_xor_sync(0xffffffffu, s, o);
        logits[e] = s;
    }
    float mx = logits[0];
    #pragma unroll
    for (int e = 1; e < NEXP; e++) mx = fmaxf(mx, logits[e]);
    float p[NEXP], sum = 0.f;
    #pragma unroll
    for (int e = 0; e < NEXP; e++) { p[e] = expf(logits[e] - mx); sum += p[e]; }
    #pragma unroll
    for (int e = 0; e < NEXP; e++) p[e] /= sum;
    int i0 = 0;
    #pragma unroll
    for (int e = 1; e < NEXP; e++) if (p[e] > p[i0]) i0 = e;
    int i1 = -1;
    #pragma unroll
    for (int e = 0; e < NEXP; e++) {
        if (e == i0) continue;
        if (i1 < 0 || p[e] > p[i1]) i1 = e;
    }
    float w0 = p[i0], w1 = p[i1], t = w0 + w1;
    if (lane == 0) {
        g_gatew[warp * 2 + 0] = w0 / t;
        g_gatew[warp * 2 + 1] = w1 / t;
        int p0 = atomicAdd(&g_counts[i0], 1);
        g_buckets[i0 * NT + p0] = warp * 2 + 0;
        int p1 = atomicAdd(&g_counts[i1], 1);
        g_buckets[i1 * NT + p1] = warp * 2 + 1;
    }
}

// ---------------- prep: streaming fp32 -> fp16 conversions -----------------
__global__ void convert_x_kernel(const float* __restrict__ x) {
    int i = blockIdx.x * blockDim.x + threadIdx.x;
    if (i >= NT * CDIM) return;
    g_x_h[i] = __float2half(x[i]);
}

// Destination pointers resolved IN DEVICE CODE (host-side &__device__ symbol
// is the host shadow address; GB300 ATS makes that a silent host write).
template <int W>
__global__ void convert_w_kernel(const float* __restrict__ src, size_t off) {
    __half* dst = W ? g_wpr16 : g_wfc16;
    size_t i = off + ((size_t)blockIdx.x * blockDim.x + threadIdx.x) * 8;
    float4 a = *(const float4*)(src + i);
    float4 b = *(const float4*)(src + i + 4);
    __half hb[8];
    hb[0] = __float2half(a.x); hb[1] = __float2half(a.y);
    hb[2] = __float2half(a.z); hb[3] = __float2half(a.w);
    hb[4] = __float2half(b.x); hb[5] = __float2half(b.y);
    hb[6] = __float2half(b.z); hb[7] = __float2half(b.w);
    *(uint4*)(dst + i) = *(uint4*)hb;
}

__device__ __forceinline__ float gelu_new(float v) {
    float u = v + 0.044715f * v * v * v;
    return 0.5f * v * (1.f + tanhf(0.7978845608028654f * u));
}

// ---------------- async chunk loader --------------------------------------
__device__ __forceinline__ void load_chunk_async(
    uint32_t stage_u32, const __half* __restrict__ A, int strideA, int eshift,
    const int* __restrict__ entryArr, const __half* __restrict__ B,
    int strideB, int n0, int k0, int tid) {
    #pragma unroll
    for (int t = 0; t < 4; t++) {        // A: 128 rows x 8 chunks
        int idx = tid + t * 256;
        int r = (idx >> 3) & 127;
        int c8 = idx & 7;
        uint32_t dst = stage_u32 + (r * ROWE + c8 * 8) * 2;
        int en = entryArr[r];
        if (en >= 0)
            cp16(dst, A + (size_t)(en >> eshift) * strideA + k0 + c8 * 8, 16);
        else
            cp16(dst, A, 0);             // zero-fill
    }
    #pragma unroll
    for (int t = 0; t < 4; t++) {        // B: 64 k-rows x 16 chunks (256B rows)
        int idx = tid + t * 256;
        int r = (idx >> 4) & 63;
        int c16 = idx & 15;
        uint32_t dst = stage_u32 + (TILEA_E + r * ROWB + c16 * 8) * 2;
        cp16(dst, B + (size_t)(k0 + r) * strideB + n0 + c16 * 8, 16);
    }
}

// ---------------- fused GEMM (software-pipelined fragments, opt split-K) ---
// P2 = 0: h = gelu(Xg @ w_fc + b_fc)  -> g_h (fp16); KS must be 1
// P2 = 1: out[token] += gate * (h @ w_proj [+ b_proj if slice 0])  (atomic)
// grid.z = (experts in launch) << LOG2KS; z encodes (expert, k-slice)
template <int P2, int LOG2KS>
__global__ __launch_bounds__(256, 2) void gemm_mma(const float* __restrict__ bias,
                                                   float* __restrict__ out,
                                                   int ebase) {
    const int NDIM = P2 ? CDIM : HDIM;
    const int KD   = P2 ? HDIM : CDIM;
    const int KS   = 1 << LOG2KS;
    const int NCHS = KD / KC / KS;       // chunks per k-slice

    int z = blockIdx.z;
    int slice = z & (KS - 1);
    int e = ebase + (z >> LOG2KS);
    int kbase = slice * NCHS;            // first chunk index of this slice

    int cnt = g_counts[e];
    int m0 = blockIdx.y * BM;
    if (m0 >= cnt) return;
    int n0 = blockIdx.x * BN;

    const __half* A = P2 ? g_h : g_x_h;
    const int eshift = P2 ? 0 : 1;
    const __half* B = P2 ? (g_wpr16 + (size_t)e * HDIM * CDIM)
                         : (g_wfc16 + (size_t)e * CDIM * HDIM);

    extern __shared__ __half sm[];
    __shared__ int entryArr[BM];
    uint32_t sbase = smem_u32(sm);

    int tid = threadIdx.x;
    int wid = tid >> 5, lane = tid & 31;
    int wm = (wid >> 2) * 64, wn = (wid & 3) * 32;
    int gr = lane >> 2, gc2 = (lane & 3) * 2;

    int a_row = (lane & 15);
    int a_cof = (lane >> 4) * 8;
    int bg = lane >> 3;
    int b_krow = (bg & 1) * 8 + (lane & 7);
    int b_ncol = (bg >> 1) * 8;

    if (tid < BM) {
        int m = m0 + tid;
        entryArr[tid] = (m < cnt) ? g_buckets[e * NT + m] : -1;
    }
    __syncthreads();

    load_chunk_async(sbase, A, KD, eshift, entryArr, B, NDIM, n0,
                     kbase * KC, tid);
    CP_COMMIT();
    load_chunk_async(sbase + (uint32_t)(STAGE_E * 2), A, KD, eshift, entryArr,
                     B, NDIM, n0, (kbase + 1) * KC, tid);
    CP_COMMIT();

    float acc[4][4][4] = {};
    int s_cur = 0, s_pf = 2;

    for (int c = 0; c < NCHS; c++) {
        CP_WAIT(1);
        __syncthreads();

        if (c + 2 < NCHS)
            load_chunk_async(sbase + (uint32_t)(s_pf * STAGE_E * 2), A, KD,
                             eshift, entryArr, B, NDIM, n0,
                             (kbase + c + 2) * KC, tid);
        CP_COMMIT();

        uint32_t st = sbase + (uint32_t)(s_cur * STAGE_E * 2);
        uint32_t stA = st;
        uint32_t stB = st + TILEA_E * 2;

        uint32_t bfb[2][8];
        uint32_t afb[2][4];

        {
            uint32_t r4[4];
            uint32_t boff0 = (uint32_t)(((b_krow) * ROWB + wn + b_ncol) * 2);
            ldm_x4_trans(r4, stB + boff0);
            bfb[0][0] = r4[0]; bfb[0][1] = r4[1];
            bfb[0][2] = r4[2]; bfb[0][3] = r4[3];
            uint32_t boff1 = (uint32_t)(((b_krow) * ROWB + wn + 16 + b_ncol) * 2);
            ldm_x4_trans(r4, stB + boff1);
            bfb[0][4] = r4[0]; bfb[0][5] = r4[1];
            bfb[0][6] = r4[2]; bfb[0][7] = r4[3];
        }
        ldm_x4(afb[0], stA + (uint32_t)(((wm + a_row) * ROWE + a_cof) * 2));

        #pragma unroll
        for (int s = 0; s < 4; s++) {
            int bcur = s & 1;
            if (s < 3) {
                int kofn = (s + 1) * 16;
                uint32_t r4[4];
                uint32_t boff0 = (uint32_t)(
                    ((kofn + b_krow) * ROWB + wn + b_ncol) * 2);
                ldm_x4_trans(r4, stB + boff0);
                bfb[bcur ^ 1][0] = r4[0]; bfb[bcur ^ 1][1] = r4[1];
                bfb[bcur ^ 1][2] = r4[2]; bfb[bcur ^ 1][3] = r4[3];
                uint32_t boff1 = (uint32_t)(
                    ((kofn + b_krow) * ROWB + wn + 16 + b_ncol) * 2);
                ldm_x4_trans(r4, stB + boff1);
                bfb[bcur ^ 1][4] = r4[0]; bfb[bcur ^ 1][5] = r4[1];
                bfb[bcur ^ 1][6] = r4[2]; bfb[bcur ^ 1][7] = r4[3];
            }
            int kof = s * 16;
            #pragma unroll
            for (int i = 0; i < 4; i++) {
                int acur = i & 1;
                if (i < 3) {
                    uint32_t aoff = (uint32_t)(
                        ((wm + (i + 1) * 16 + a_row) * ROWE + kof + a_cof) * 2);
                    ldm_x4(afb[acur ^ 1], stA + aoff);
                } else if (s < 3) {
                    uint32_t aoff = (uint32_t)(
                        ((wm + a_row) * ROWE + (s + 1) * 16 + a_cof) * 2);
                    ldm_x4(afb[acur ^ 1], stA + aoff);
                }
                #pragma unroll
                for (int j = 0; j < 4; j++)
                    mma_fp16(acc[i][j], afb[acur], &bfb[bcur][j * 2]);
            }
        }
        s_cur = (s_cur == 2) ? 0 : s_cur + 1;
        s_pf  = (s_pf == 2) ? 0 : s_pf + 1;
    }

    // epilogue: acc frag (row = wm+i*16+gr+h2*8, col = wn+j*8+gc2+{0,1})
    float bs[4][2];
    #pragma unroll
    for (int j = 0; j < 4; j++) {
        int n = n0 + wn + j * 8 + gc2;
        float b0 = bias[e * NDIM + n];
        float b1 = bias[e * NDIM + n + 1];
        bs[j][0] = (slice == 0) ? b0 : 0.f;   // bias only once across slices
        bs[j][1] = (slice == 0) ? b1 : 0.f;
    }
    #pragma unroll
    for (int i = 0; i < 4; i++) {
        #pragma unroll
        for (int h2 = 0; h2 < 2; h2++) {
            int lr = wm + i * 16 + gr + h2 * 8;
            int entry = entryArr[lr];
            if (entry < 0) continue;
            if (P2 == 0) {
                uint32_t* dh = (uint32_t*)(g_h + (size_t)entry * HDIM + n0 + wn);
                #pragma unroll
                for (int j = 0; j < 4; j++) {
                    float v0 = acc[i][j][h2 * 2 + 0] + bs[j][0];
                    float v1 = acc[i][j][h2 * 2 + 1] + bs[j][1];
                    __half q0 = __float2half(gelu_new(v0));
                    __half q1 = __float2half(gelu_new(v1));
                    dh[(j * 8 + gc2) >> 1] =
                        ((uint32_t)__half_as_ushort(q1) << 16) |
                        __half_as_ushort(q0);
                }
            } else {
                float ga = g_gatew[entry];
                float* yt = out + (size_t)(entry >> 1) * CDIM + n0 + wn;
                #pragma unroll
                for (int j = 0; j < 4; j++) {
                    float y0 = ga * (acc[i][j][h2 * 2 + 0] + bs[j][0]);
                    float y1 = ga * (acc[i][j][h2 * 2 + 1] + bs[j][1]);
                    atomicAdd(&yt[j * 8 + gc2], y0);
                    atomicAdd(&yt[j * 8 + gc2 + 1], y1);
                }
            }
        }
    }
}

// ---------------- launch (fork/join DAG, capture-safe) ---------------------
extern "C" void kernel_launch(void* const* d_in, const int* in_sizes, int n_in,
                              void* d_out, int out_size) {
    const float* x      = (const float*)d_in[0];
    const float* rw     = (const float*)d_in[1];
    const float* w_fc   = (const float*)d_in[2];
    const float* b_fc   = (const float*)d_in[3];
    const float* w_proj = (const float*)d_in[4];
    const float* b_proj = (const float*)d_in[5];
    float* out = (float*)d_out;

    cudaFuncSetAttribute((const void*)gemm_mma<0, 0>,
                         cudaFuncAttributeMaxDynamicSharedMemorySize, SMEM_DYN);
    cudaFuncSetAttribute((const void*)gemm_mma<1, 0>,
                         cudaFuncAttributeMaxDynamicSharedMemorySize, SMEM_DYN);
    cudaFuncSetAttribute((const void*)gemm_mma<1, 1>,
                         cudaFuncAttributeMaxDynamicSharedMemorySize, SMEM_DYN);

    const size_t WHALF = (size_t)(NEXP / 2) * CDIM * HDIM;
    const int WGRID = (int)(WHALF / 8 / 256);
    const dim3 G1(HDIM / BN, NT / BM, NEXP / 2);
    const dim3 G2a(CDIM / BN, NT / BM, NEXP / 2);          // KS=1 (packed phase)
    const dim3 G2b(CDIM / BN, NT / BM, (NEXP / 2) << 1);   // KS=2 (tail phase)

    // fork
    cudaEventRecord(g_ss.evFork, 0);
    cudaStreamWaitEvent(g_ss.s1, g_ss.evFork, 0);
    cudaStreamWaitEvent(g_ss.s2, g_ss.evFork, 0);
    cudaStreamWaitEvent(g_ss.s3, g_ss.evFork, 0);

    convert_w_kernel<0><<<WGRID, 256, 0, g_ss.s1>>>(w_fc, 0);
    cudaEventRecord(g_ss.evW0a, g_ss.s1);
    convert_w_kernel<0><<<WGRID, 256, 0, g_ss.s1>>>(w_fc, WHALF);
    cudaEventRecord(g_ss.evW0b, g_ss.s1);
    convert_w_kernel<1><<<WGRID, 256, 0, g_ss.s2>>>(w_proj, 0);
    cudaEventRecord(g_ss.evW1a, g_ss.s2);
    convert_w_kernel<1><<<WGRID, 256, 0, g_ss.s2>>>(w_proj, WHALF);
    cudaEventRecord(g_ss.evW1b, g_ss.s2);
    convert_x_kernel<<<(NT * CDIM + 255) / 256, 256, 0, g_ss.s3>>>(x);
    cudaMemsetAsync(out, 0, (size_t)NT * CDIM * sizeof(float), g_ss.s3);
    cudaEventRecord(g_ss.evCX, g_ss.s3);

    // main: routing
    init_kernel<<<1, 32>>>();
    router_kernel<<<NT / 2, 64>>>(x, rw);

    cudaStreamWaitEvent(0, g_ss.evW0a, 0);
    cudaStreamWaitEvent(0, g_ss.evCX, 0);
    gemm_mma<0, 0><<<G1, 256, SMEM_DYN>>>(b_fc, out, 0);
    cudaEventRecord(g_ss.evG1a, 0);

    // gemm2a (KS=1) overlaps gemm1b in the packed middle phase
    cudaStreamWaitEvent(g_ss.s1, g_ss.evG1a, 0);
    cudaStreamWaitEvent(g_ss.s1, g_ss.evW1a, 0);
    gemm_mma<1, 0><<<G2a, 256, SMEM_DYN, g_ss.s1>>>(b_proj, out, 0);
    cudaEventRecord(g_ss.evG2a, g_ss.s1);

    cudaStreamWaitEvent(0, g_ss.evW0b, 0);
    gemm_mma<0, 0><<<G1, 256, SMEM_DYN>>>(b_fc, out, 4);
    // gemm2b (KS=2): the unbackfillable tail — shorter CTAs shrink it
    cudaStreamWaitEvent(0, g_ss.evW1b, 0);
    gemm_mma<1, 1><<<G2b, 256, SMEM_DYN>>>(b_proj, out, 4);

    cudaStreamWaitEvent(0, g_ss.evG2a, 0);
}